// round 16
// baseline (speedup 1.0000x reference)
#include <cuda_runtime.h>
#include <cuda_bf16.h>
#include <cstdint>

#define T_STEPS 16384
#define F_IN    2048
#define HD      16
#define GD      48
#define LN      6
#define AD      64
#define WROW    36   // per-lane packed weight slot: 16 prim + 16 n + 4 pad
#define NT      256  // 8 warps

typedef unsigned long long ull;

// precomputed layer-0 input projection; prim rows (g<32) pre-scaled by 0.5
__device__ float g_GI0[T_STEPS * GD];

// Early energy pairs (l <= 3) over worker warps 1..7 (R14 balance)
__constant__ int c_NE[7]  = {0, 0, 1, 2, 3, 2, 2};
__constant__ int c_OFF[7] = {0, 0, 0, 1, 3, 6, 8};
__constant__ int c_PI[10] = {0, 0, 0, 0, 1,1, 1,2, 2,3};
__constant__ int c_PL[10] = {0, 1, 2, 3, 1,2, 3,2, 3,3};

__device__ __forceinline__ float tanh_mufu(float x) {
    float r; asm("tanh.approx.f32 %0, %1;" : "=f"(r) : "f"(x));
    return r;
}

__device__ __forceinline__ ull ffma2(ull a, ull b, ull c) {
    ull d; asm("fma.rn.f32x2 %0, %1, %2, %3;" : "=l"(d) : "l"(a), "l"(b), "l"(c));
    return d;
}
__device__ __forceinline__ ull fadd2(ull a, ull b) {
    ull d; asm("add.rn.f32x2 %0, %1, %2;" : "=l"(d) : "l"(a), "l"(b));
    return d;
}
__device__ __forceinline__ ull pk(float lo, float hi) {
    ull d; asm("mov.b64 %0, {%1, %2};" : "=l"(d) : "f"(lo), "f"(hi));
    return d;
}
__device__ __forceinline__ float hsum(ull v) {
    float lo, hi; asm("mov.b64 {%0, %1}, %2;" : "=f"(lo), "=f"(hi) : "l"(v));
    return lo + hi;
}

__device__ __forceinline__ void bar_sync(int id, int cnt) {
    asm volatile("bar.sync %0, %1;" :: "r"(id), "r"(cnt) : "memory");
}
__device__ __forceinline__ void bar_arrive(int id, int cnt) {
    asm volatile("bar.arrive %0, %1;" :: "r"(id), "r"(cnt) : "memory");
}

// ---------------------------------------------------------------------------
// Kernel 1: GI0[t][g] = (b_ih0[g] + sum_f batch[t][f]*W_ih0[g][f]) * (g<32 ? 0.5 : 1)
// ---------------------------------------------------------------------------
__global__ __launch_bounds__(256) void k_gi0(
    const float* __restrict__ batch,
    const float* __restrict__ Wih0,
    const float* __restrict__ bih0)
{
    __shared__ float Bs[32 * 65];
    __shared__ float Ws[48 * 64];
    const int t0  = blockIdx.x * 32;
    const int tid = threadIdx.x;
    const int tl  = tid & 31;
    const int gg  = tid >> 5;
    const int g0  = gg * 6;

    float acc[6];
#pragma unroll
    for (int j = 0; j < 6; j++) acc[j] = 0.f;

    for (int k0 = 0; k0 < F_IN; k0 += 64) {
        __syncthreads();
#pragma unroll
        for (int i = 0; i < 8; i++) {
            int idx = tid + i * 256;
            int r = idx >> 6, c = idx & 63;
            Bs[r * 65 + c] = batch[(t0 + r) * F_IN + k0 + c];
        }
#pragma unroll
        for (int i = 0; i < 12; i++) {
            int idx = tid + i * 256;
            int r = idx >> 6, c = idx & 63;
            Ws[r * 64 + c] = Wih0[r * F_IN + k0 + c];
        }
        __syncthreads();
#pragma unroll 4
        for (int kk = 0; kk < 64; kk++) {
            float b = Bs[tl * 65 + kk];
#pragma unroll
            for (int j = 0; j < 6; j++) acc[j] += b * Ws[(g0 + j) * 64 + kk];
        }
    }
#pragma unroll
    for (int j = 0; j < 6; j++) {
        float sc = (g0 + j < 32) ? 0.5f : 1.0f;
        g_GI0[(t0 + tl) * GD + g0 + j] = (acc[j] + bih0[g0 + j]) * sc;
    }
}

// ---------------------------------------------------------------------------
// Kernel 2: persistent single-block scan, 3-barrier pipeline (256 threads).
// ---------------------------------------------------------------------------
struct Smem {
    float Wih2[5 * 32 * WROW];   // layers1..5 per-lane [prim16(x0.5)|n16|pad4]
    float Whh2[6 * 32 * WROW];   // prim rows pre-scaled 0.5
    float Wac [6 * 64 * 18];     // attention weights column-major, col slot 18
    float fc1r[32 * 20];
    float ba  [6 * 64];
    float va  [6 * 64];
    float bihN [5 * 16];
    float bhhPr[6 * 32];         // 0.5*(b_hh prim + b_ih prim)
    float bhhN [6 * 16];
    float fc1b[32];
    float fc2 [32];
    float fc2b;
    float pad1[3];
    float h   [6 * 16];
    float newS[6 * 16];
    float ghP [6 * 32];          // published: 0.5*(Whh_p.h + b_hh_p + b_ih_p)
    float ghN [6 * 16];          // published: Whh_n.h + b_hhN
    float e   [36];              // early (l<=3) energies
};

__global__ __launch_bounds__(NT, 1) void k_scan(
    const float* __restrict__ h0,
    const float* __restrict__ W_hh0,
    const float* __restrict__ b_hh0,
    const float* __restrict__ W_ih,
    const float* __restrict__ W_hh,
    const float* __restrict__ b_ih,
    const float* __restrict__ b_hh,
    const float* __restrict__ Wa,
    const float* __restrict__ ba,
    const float* __restrict__ va,
    const float* __restrict__ fc1_w,
    const float* __restrict__ fc1_b,
    const float* __restrict__ fc2_w,
    const float* __restrict__ fc2_b,
    float* __restrict__ out)
{
    extern __shared__ char smem_raw[];
    Smem* s = reinterpret_cast<Smem*>(smem_raw);

    const int tid  = threadIdx.x;
    const int warp = tid >> 5;
    const int lane = tid & 31;
    const int jlow = lane & 15;
    const unsigned FULL = 0xffffffffu;

    // ---------------- build packed layouts in shared (once) ----------------
    for (int idx = tid; idx < 5 * 32 * 16; idx += NT) {
        int hh = idx & 15, r = idx >> 4;
        int l = r >> 5, ln = r & 31;
        s->Wih2[r * WROW + hh]      = 0.5f * W_ih[l * 768 + ln * 16 + hh];
        s->Wih2[r * WROW + 16 + hh] = (ln < 16) ? W_ih[l * 768 + (32 + ln) * 16 + hh] : 0.f;
    }
    for (int idx = tid; idx < 6 * 32 * 16; idx += NT) {
        int hh = idx & 15, r = idx >> 4;
        int i = r >> 5, ln = r & 31;
        float prim, nw;
        if (i == 0) {
            prim = W_hh0[ln * 16 + hh];
            nw   = (ln < 16) ? W_hh0[(32 + ln) * 16 + hh] : 0.f;
        } else {
            prim = W_hh[(i - 1) * 768 + ln * 16 + hh];
            nw   = (ln < 16) ? W_hh[(i - 1) * 768 + (32 + ln) * 16 + hh] : 0.f;
        }
        s->Whh2[r * WROW + hh]      = 0.5f * prim;
        s->Whh2[r * WROW + 16 + hh] = nw;
    }
    for (int idx = tid; idx < 6 * 16 * 64; idx += NT) {
        int i = idx >> 10;
        int rem = idx & 1023;
        int hh = rem >> 6, col = rem & 63;
        s->Wac[(i * 64 + col) * 18 + hh] = Wa[idx];
    }
    for (int idx = tid; idx < 32 * 16; idx += NT) {
        int row = idx >> 4, hh = idx & 15;
        s->fc1r[row * 20 + hh] = fc1_w[idx];
    }
    for (int idx = tid; idx < 6 * 64; idx += NT) { s->ba[idx] = ba[idx]; s->va[idx] = va[idx]; }
    for (int idx = tid; idx < 5 * 16; idx += NT) {
        int l = idx >> 4, j = idx & 15;
        s->bihN[idx] = b_ih[l * 48 + 32 + j];
    }
    for (int idx = tid; idx < 6 * 32; idx += NT) {
        int i = idx >> 5, ln = idx & 31;
        float bp = (i == 0) ? b_hh0[ln] : b_hh[(i - 1) * 48 + ln];
        float bi = (i == 0) ? 0.f : b_ih[(i - 1) * 48 + ln];
        s->bhhPr[idx] = 0.5f * (bp + bi);
    }
    for (int idx = tid; idx < 6 * 16; idx += NT) {
        int i = idx >> 4, j = idx & 15;
        s->bhhN[idx] = (i == 0) ? b_hh0[32 + j] : b_hh[(i - 1) * 48 + 32 + j];
    }
    if (tid < 32) { s->fc1b[tid] = fc1_b[tid]; s->fc2[tid] = fc2_w[tid]; }
    if (tid == 0) s->fc2b = fc2_b[0];
    for (int idx = tid; idx < 6 * 16; idx += NT) s->h[idx] = h0[idx];
    __syncthreads();

    // ---------------- initial gh for step 0 (warps 1..6, i = warp-1) -------
    if (warp >= 1 && warp <= 6) {
        const int i = warp - 1;
        const float* wl = &s->Whh2[(i * 32 + lane) * WROW];
        const ulonglong2* wpv = (const ulonglong2*)wl;
        const ulonglong2* wnv = (const ulonglong2*)(wl + 16);
        const ull* ip = (const ull*)&s->h[i * 16];
        ull p0 = 0ull, p1 = 0ull, q0 = 0ull, q1 = 0ull;
#pragma unroll
        for (int k = 0; k < 4; k++) {
            ulonglong2 wp = wpv[k], wn = wnv[k];
            ull x0 = ip[2 * k], x1 = ip[2 * k + 1];
            p0 = ffma2(wp.x, x0, p0); p1 = ffma2(wp.y, x1, p1);
            q0 = ffma2(wn.x, x0, q0); q1 = ffma2(wn.y, x1, q1);
        }
        s->ghP[i * 32 + lane] = hsum(fadd2(p0, p1)) + s->bhhPr[i * 32 + lane];
        if (lane < 16)
            s->ghN[i * 16 + lane] = hsum(fadd2(q0, q1)) + s->bhhN[i * 16 + lane];
    }
    __syncthreads();

    // =========================== pipeline ===========================
    if (warp == 0) {
        // ------------------ GRU-chain warp (shuffle handoff) ------------------
        float gp_cur = g_GI0[lane];
        float gn_cur = g_GI0[32 + jlow];
        ull X[8];

        for (int t = 0; t < T_STEPS; t++) {
            float gp_nxt = 0.f, gn_nxt = 0.f;
            if (t + 1 < T_STEPS) {
                gp_nxt = g_GI0[(t + 1) * GD + lane];
                gn_nxt = g_GI0[(t + 1) * GD + 32 + jlow];
            }

            // layer 0 (gi in registers)
            {
                float ap = gp_cur + s->ghP[lane];
                float gv = fmaf(tanh_mufu(ap), 0.5f, 0.5f);
                float zv = __shfl_sync(FULL, gv, 16 + jlow);
                float an = fmaf(gv, s->ghN[jlow], gn_cur);
                float n  = tanh_mufu(an);
                float hp = s->h[jlow];
                float newh = n + zv * (hp - n);
                if (lane < 16) s->newS[lane] = newh;
#pragma unroll
                for (int k = 0; k < 8; k++)
                    X[k] = pk(__shfl_sync(FULL, newh, 2 * k),
                              __shfl_sync(FULL, newh, 2 * k + 1));
            }
            // layers 1..5 (inputs in X registers; no per-layer syncwarp)
#pragma unroll
            for (int l = 1; l < LN; l++) {
                const float* wl = &s->Wih2[((l - 1) * 32 + lane) * WROW];
                const ulonglong2* wpv = (const ulonglong2*)wl;
                const ulonglong2* wnv = (const ulonglong2*)(wl + 16);
                float ghn = s->ghN[l * 16 + jlow];
                float hp  = s->h[l * 16 + jlow];
                ull p0 = pk(s->ghP[l * 32 + lane], 0.f), p1 = 0ull;
                ull q0 = pk(s->bihN[(l - 1) * 16 + jlow], 0.f), q1 = 0ull;
#pragma unroll
                for (int k = 0; k < 4; k++) {
                    ulonglong2 wp = wpv[k], wn = wnv[k];
                    p0 = ffma2(wp.x, X[2 * k], p0); p1 = ffma2(wp.y, X[2 * k + 1], p1);
                    q0 = ffma2(wn.x, X[2 * k], q0); q1 = ffma2(wn.y, X[2 * k + 1], q1);
                }
                float ap = hsum(fadd2(p0, p1));
                float gv = fmaf(tanh_mufu(ap), 0.5f, 0.5f);
                float zv = __shfl_sync(FULL, gv, 16 + jlow);
                float an = fmaf(gv, ghn, hsum(fadd2(q0, q1)));
                float n  = tanh_mufu(an);
                float newh = n + zv * (hp - n);
                if (lane < 16) s->newS[l * 16 + lane] = newh;
                if (l < 5) {
#pragma unroll
                    for (int k = 0; k < 8; k++)
                        X[k] = pk(__shfl_sync(FULL, newh, 2 * k),
                                  __shfl_sync(FULL, newh, 2 * k + 1));
                }
                if (l == 3) { __syncwarp(); bar_arrive(1, NT); }
            }
            __syncwarp();
            bar_arrive(2, NT);                      // newS[4..5] ready
            bar_sync(3, NT);                        // wait for publishes

            gp_cur = gp_nxt; gn_cur = gn_nxt;
        }
    } else if (warp <= 6) {
        // ------------------ combine warp for layer i = warp-1 ------------------
        const int i = warp - 1;
        ulonglong2 wp_[4], wn_[4];
        {
            const float* whl = &s->Whh2[(i * 32 + lane) * WROW];
            const ulonglong2* wpv = (const ulonglong2*)whl;
            const ulonglong2* wnv = (const ulonglong2*)(whl + 16);
#pragma unroll
            for (int k = 0; k < 4; k++) { wp_[k] = wpv[k]; wn_[k] = wnv[k]; }
        }
        const float bhhP_l = s->bhhPr[i * 32 + lane];
        const float bhhN_l = s->bhhN[i * 16 + jlow];
        const int ne = c_NE[warp - 1], off = c_OFF[warp - 1];

        auto ghS_term = [&](const float* base, float& P, float& N, float& S) {
            const ull* ip = (const ull*)base;
            S = base[jlow];
            ull p0 = 0ull, p1 = 0ull, q0 = 0ull, q1 = 0ull;
#pragma unroll
            for (int k = 0; k < 4; k++) {
                ull x0 = ip[2 * k], x1 = ip[2 * k + 1];
                p0 = ffma2(wp_[k].x, x0, p0); p1 = ffma2(wp_[k].y, x1, p1);
                q0 = ffma2(wn_[k].x, x0, q0); q1 = ffma2(wn_[k].y, x1, q1);
            }
            P = hsum(fadd2(p0, p1));
            N = hsum(fadd2(q0, q1));
        };

        auto energy1 = [&](int ii, int ll) -> float {
            const ull* ip = (const ull*)&s->newS[ll * 16];
            const ull* wa0 = (const ull*)&s->Wac[(ii * 64 + lane) * 18];
            const ull* wa1 = (const ull*)&s->Wac[(ii * 64 + lane + 32) * 18];
            ull a0 = 0ull, a1 = 0ull, a2 = 0ull, a3 = 0ull;
#pragma unroll
            for (int k = 0; k < 4; k++) {
                ull x0 = ip[2 * k], x1 = ip[2 * k + 1];
                a0 = ffma2(wa0[2 * k], x0, a0); a1 = ffma2(wa0[2 * k + 1], x1, a1);
                a2 = ffma2(wa1[2 * k], x0, a2); a3 = ffma2(wa1[2 * k + 1], x1, a3);
            }
            float e0 = hsum(fadd2(a0, a1)) + s->ba[ii * 64 + lane];
            float e1 = hsum(fadd2(a2, a3)) + s->ba[ii * 64 + lane + 32];
            float v = tanh_mufu(e0) * s->va[ii * 64 + lane]
                    + tanh_mufu(e1) * s->va[ii * 64 + lane + 32];
#pragma unroll
            for (int o = 16; o; o >>= 1) v += __shfl_xor_sync(FULL, v, o);
            return v;
        };
        auto energy2 = [&](int iA, int lA, int iB, int lB, float& vA, float& vB) {
            const ull* ipA = (const ull*)&s->newS[lA * 16];
            const ull* ipB = (const ull*)&s->newS[lB * 16];
            const ull* wA0 = (const ull*)&s->Wac[(iA * 64 + lane) * 18];
            const ull* wA1 = (const ull*)&s->Wac[(iA * 64 + lane + 32) * 18];
            const ull* wB0 = (const ull*)&s->Wac[(iB * 64 + lane) * 18];
            const ull* wB1 = (const ull*)&s->Wac[(iB * 64 + lane + 32) * 18];
            ull a0 = 0ull, a1 = 0ull, a2 = 0ull, a3 = 0ull;
            ull b0 = 0ull, b1 = 0ull, b2 = 0ull, b3 = 0ull;
#pragma unroll
            for (int k = 0; k < 4; k++) {
                ull xA0 = ipA[2 * k], xA1 = ipA[2 * k + 1];
                ull xB0 = ipB[2 * k], xB1 = ipB[2 * k + 1];
                a0 = ffma2(wA0[2 * k], xA0, a0); a1 = ffma2(wA0[2 * k + 1], xA1, a1);
                a2 = ffma2(wA1[2 * k], xA0, a2); a3 = ffma2(wA1[2 * k + 1], xA1, a3);
                b0 = ffma2(wB0[2 * k], xB0, b0); b1 = ffma2(wB0[2 * k + 1], xB1, b1);
                b2 = ffma2(wB1[2 * k], xB0, b2); b3 = ffma2(wB1[2 * k + 1], xB1, b3);
            }
            float eA0 = hsum(fadd2(a0, a1)) + s->ba[iA * 64 + lane];
            float eA1 = hsum(fadd2(a2, a3)) + s->ba[iA * 64 + lane + 32];
            float eB0 = hsum(fadd2(b0, b1)) + s->ba[iB * 64 + lane];
            float eB1 = hsum(fadd2(b2, b3)) + s->ba[iB * 64 + lane + 32];
            vA = tanh_mufu(eA0) * s->va[iA * 64 + lane]
               + tanh_mufu(eA1) * s->va[iA * 64 + lane + 32];
            vB = tanh_mufu(eB0) * s->va[iB * 64 + lane]
               + tanh_mufu(eB1) * s->va[iB * 64 + lane + 32];
#pragma unroll
            for (int o = 16; o; o >>= 1) {
                vA += __shfl_xor_sync(FULL, vA, o);
                vB += __shfl_xor_sync(FULL, vB, o);
            }
        };

        for (int t = 0; t < T_STEPS; t++) {
            bar_sync(1, NT);                 // newS[0..3] of step t visible

            float gP[6], gN[6], sv[6];
#pragma unroll
            for (int l = 0; l < 4; l++)
                if (l >= i) ghS_term(&s->newS[l * 16], gP[l], gN[l], sv[l]);
            if (ne == 1) {
                float v = energy1(c_PI[off], c_PL[off]);
                if (lane == 0) s->e[c_PI[off] * 6 + c_PL[off]] = v;
            } else if (ne == 2) {
                float vX, vY;
                energy2(c_PI[off], c_PL[off], c_PI[off + 1], c_PL[off + 1], vX, vY);
                if (lane == 0) {
                    s->e[c_PI[off] * 6 + c_PL[off]] = vX;
                    s->e[c_PI[off + 1] * 6 + c_PL[off + 1]] = vY;
                }
            } else if (ne == 3) {
                float vX, vY;
                energy2(c_PI[off], c_PL[off], c_PI[off + 1], c_PL[off + 1], vX, vY);
                float vZ = energy1(c_PI[off + 2], c_PL[off + 2]);
                if (lane == 0) {
                    s->e[c_PI[off] * 6 + c_PL[off]] = vX;
                    s->e[c_PI[off + 1] * 6 + c_PL[off + 1]] = vY;
                    s->e[c_PI[off + 2] * 6 + c_PL[off + 2]] = vZ;
                }
            }

            bar_sync(2, NT);                 // newS[4..5] + all early e visible

            if (i < 5) {
                // ---- fused tail: one pass over x4/x5 + shared Wa columns ----
                const ull* ip4 = (const ull*)&s->newS[4 * 16];
                const ull* ip5 = (const ull*)&s->newS[5 * 16];
                ull x4[8], x5[8];
#pragma unroll
                for (int k = 0; k < 8; k++) { x4[k] = ip4[k]; x5[k] = ip5[k]; }
                sv[4] = s->newS[4 * 16 + jlow];
                sv[5] = s->newS[5 * 16 + jlow];
                const ull* wa0 = (const ull*)&s->Wac[(i * 64 + lane) * 18];
                const ull* wa1 = (const ull*)&s->Wac[(i * 64 + lane + 32) * 18];
                ull p40 = 0ull, p41 = 0ull, q40 = 0ull, q41 = 0ull;
                ull p50 = 0ull, p51 = 0ull, q50 = 0ull, q51 = 0ull;
                ull a0 = 0ull, a1 = 0ull, a2 = 0ull, a3 = 0ull;
                ull b0 = 0ull, b1 = 0ull, b2 = 0ull, b3 = 0ull;
#pragma unroll
                for (int k = 0; k < 4; k++) {
                    ull w0 = wa0[2 * k], w1 = wa0[2 * k + 1];
                    ull u0 = wa1[2 * k], u1 = wa1[2 * k + 1];
                    ull x40 = x4[2 * k], x41 = x4[2 * k + 1];
                    ull x50 = x5[2 * k], x51 = x5[2 * k + 1];
                    p40 = ffma2(wp_[k].x, x40, p40); p41 = ffma2(wp_[k].y, x41, p41);
                    q40 = ffma2(wn_[k].x, x40, q40); q41 = ffma2(wn_[k].y, x41, q41);
                    p50 = ffma2(wp_[k].x, x50, p50); p51 = ffma2(wp_[k].y, x51, p51);
                    q50 = ffma2(wn_[k].x, x50, q50); q51 = ffma2(wn_[k].y, x51, q51);
                    a0 = ffma2(w0, x40, a0); a1 = ffma2(w1, x41, a1);
                    a2 = ffma2(u0, x40, a2); a3 = ffma2(u1, x41, a3);
                    b0 = ffma2(w0, x50, b0); b1 = ffma2(w1, x51, b1);
                    b2 = ffma2(u0, x50, b2); b3 = ffma2(u1, x51, b3);
                }
                gP[4] = hsum(fadd2(p40, p41)); gN[4] = hsum(fadd2(q40, q41));
                gP[5] = hsum(fadd2(p50, p51)); gN[5] = hsum(fadd2(q50, q51));
                float bac0 = s->ba[i * 64 + lane], bac1 = s->ba[i * 64 + lane + 32];
                float vac0 = s->va[i * 64 + lane], vac1 = s->va[i * 64 + lane + 32];
                float vA = tanh_mufu(hsum(fadd2(a0, a1)) + bac0) * vac0
                         + tanh_mufu(hsum(fadd2(a2, a3)) + bac1) * vac1;
                float vB = tanh_mufu(hsum(fadd2(b0, b1)) + bac0) * vac0
                         + tanh_mufu(hsum(fadd2(b2, b3)) + bac1) * vac1;
#pragma unroll
                for (int o = 16; o; o >>= 1) {
                    vA += __shfl_xor_sync(FULL, vA, o);
                    vB += __shfl_xor_sync(FULL, vB, o);
                }
                // softmax without max-subtraction (|e| bounded ~5)
                float evl[6];
                evl[4] = vA; evl[5] = vB;
#pragma unroll
                for (int l = 0; l < 4; l++)
                    if (l >= i) evl[l] = s->e[i * 6 + l];
                float wv[6], ssum = 0.f;
#pragma unroll
                for (int l = 0; l < 6; l++)
                    if (l >= i) { wv[l] = __expf(evl[l]); ssum += wv[l]; }
                float inv = __fdividef(1.f, ssum);
                float sP = 0.f, sN = 0.f, sH = 0.f;
#pragma unroll
                for (int l = 0; l < 6; l++)
                    if (l >= i) {
                        sP += wv[l] * gP[l];
                        sN += wv[l] * gN[l];
                        sH += wv[l] * sv[l];
                    }
                s->ghP[i * 32 + lane] = bhhP_l + sP * inv;
                if (lane < 16) {
                    s->ghN[i * 16 + lane] = bhhN_l + sN * inv;
                    s->h[i * 16 + lane]   = sH * inv;
                }
            } else {
                // i = 5: h_next = newS[5]; gh direct
                ghS_term(&s->newS[5 * 16], gP[5], gN[5], sv[5]);
                s->ghP[5 * 32 + lane] = bhhP_l + gP[5];
                if (lane < 16) {
                    s->ghN[5 * 16 + lane] = bhhN_l + gN[5];
                    s->h[5 * 16 + lane]   = sv[5];
                }
            }
            __syncwarp();
            bar_arrive(3, NT);               // step-(t+1) state published
        }
    } else {
        // ------------------ warp 7: early energies + FC head ------------------
        const int off = c_OFF[6];
        const ull* fw = (const ull*)&s->fc1r[lane * 20];
        const float fc1b_l = s->fc1b[lane], fc2_l = s->fc2[lane];

        auto energy1 = [&](int ii, int ll) -> float {
            const ull* ip = (const ull*)&s->newS[ll * 16];
            const ull* wa0 = (const ull*)&s->Wac[(ii * 64 + lane) * 18];
            const ull* wa1 = (const ull*)&s->Wac[(ii * 64 + lane + 32) * 18];
            ull a0 = 0ull, a1 = 0ull, a2 = 0ull, a3 = 0ull;
#pragma unroll
            for (int k = 0; k < 4; k++) {
                ull x0 = ip[2 * k], x1 = ip[2 * k + 1];
                a0 = ffma2(wa0[2 * k], x0, a0); a1 = ffma2(wa0[2 * k + 1], x1, a1);
                a2 = ffma2(wa1[2 * k], x0, a2); a3 = ffma2(wa1[2 * k + 1], x1, a3);
            }
            float e0 = hsum(fadd2(a0, a1)) + s->ba[ii * 64 + lane];
            float e1 = hsum(fadd2(a2, a3)) + s->ba[ii * 64 + lane + 32];
            float v = tanh_mufu(e0) * s->va[ii * 64 + lane]
                    + tanh_mufu(e1) * s->va[ii * 64 + lane + 32];
#pragma unroll
            for (int o = 16; o; o >>= 1) v += __shfl_xor_sync(FULL, v, o);
            return v;
        };

        for (int t = 0; t < T_STEPS; t++) {
            bar_sync(1, NT);
            {
                float v0 = energy1(c_PI[off], c_PL[off]);
                float v1 = energy1(c_PI[off + 1], c_PL[off + 1]);
                if (lane == 0) {
                    s->e[c_PI[off] * 6 + c_PL[off]] = v0;
                    s->e[c_PI[off + 1] * 6 + c_PL[off + 1]] = v1;
                }
            }
            bar_sync(2, NT);                 // newS[5] visible
            {
                const ull* ip = (const ull*)&s->newS[5 * 16];
                ull a0 = 0ull, a1 = 0ull;
#pragma unroll
                for (int k = 0; k < 4; k++) {
                    a0 = ffma2(fw[2 * k], ip[2 * k], a0);
                    a1 = ffma2(fw[2 * k + 1], ip[2 * k + 1], a1);
                }
                float acc = (hsum(fadd2(a0, a1)) + fc1b_l) * fc2_l;
#pragma unroll
                for (int o = 16; o; o >>= 1)
                    acc += __shfl_xor_sync(FULL, acc, o);
                if (lane == 0) out[t] = acc + s->fc2b;
            }
            __syncwarp();
            bar_arrive(3, NT);
        }
    }
}

// ---------------------------------------------------------------------------
extern "C" void kernel_launch(void* const* d_in, const int* in_sizes, int n_in,
                              void* d_out, int out_size)
{
    const float* batch  = (const float*)d_in[0];
    const float* h0     = (const float*)d_in[1];
    const float* W_ih0  = (const float*)d_in[2];
    const float* W_hh0  = (const float*)d_in[3];
    const float* b_ih0  = (const float*)d_in[4];
    const float* b_hh0  = (const float*)d_in[5];
    const float* W_ih   = (const float*)d_in[6];
    const float* W_hh   = (const float*)d_in[7];
    const float* b_ih   = (const float*)d_in[8];
    const float* b_hh   = (const float*)d_in[9];
    const float* Wa     = (const float*)d_in[10];
    const float* ba     = (const float*)d_in[11];
    const float* va     = (const float*)d_in[12];
    const float* fc1_w  = (const float*)d_in[13];
    const float* fc1_b  = (const float*)d_in[14];
    const float* fc2_w  = (const float*)d_in[15];
    const float* fc2_b  = (const float*)d_in[16];
    float* out = (float*)d_out;

    cudaFuncSetAttribute(k_scan, cudaFuncAttributeMaxDynamicSharedMemorySize,
                         (int)sizeof(Smem));

    k_gi0<<<T_STEPS / 32, 256>>>(batch, W_ih0, b_ih0);
    k_scan<<<1, NT, sizeof(Smem)>>>(h0, W_hh0, b_hh0, W_ih, W_hh, b_ih, b_hh,
                                    Wa, ba, va, fc1_w, fc1_b, fc2_w, fc2_b, out);
}

// round 17
// speedup vs baseline: 1.0511x; 1.0511x over previous
#include <cuda_runtime.h>
#include <cuda_bf16.h>
#include <cstdint>

#define T_STEPS 16384
#define F_IN    2048
#define HD      16
#define GD      48
#define LN      6
#define AD      64
#define WROW    36   // per-lane packed weight slot: 16 prim + 16 n + 4 pad
#define NT      256  // 8 warps

typedef unsigned long long ull;

// precomputed layer-0 input projection; prim rows (g<32) pre-scaled by 0.5
__device__ float g_GI0[T_STEPS * GD];

// Early energy pairs (l <= 3) over worker warps 1..7 (R14 balance)
__constant__ int c_NE[7]  = {0, 0, 1, 2, 3, 2, 2};
__constant__ int c_OFF[7] = {0, 0, 0, 1, 3, 6, 8};
__constant__ int c_PI[10] = {0, 0, 0, 0, 1,1, 1,2, 2,3};
__constant__ int c_PL[10] = {0, 1, 2, 3, 1,2, 3,2, 3,3};

__device__ __forceinline__ float tanh_mufu(float x) {
    float r; asm("tanh.approx.f32 %0, %1;" : "=f"(r) : "f"(x));
    return r;
}

__device__ __forceinline__ ull ffma2(ull a, ull b, ull c) {
    ull d; asm("fma.rn.f32x2 %0, %1, %2, %3;" : "=l"(d) : "l"(a), "l"(b), "l"(c));
    return d;
}
__device__ __forceinline__ ull fadd2(ull a, ull b) {
    ull d; asm("add.rn.f32x2 %0, %1, %2;" : "=l"(d) : "l"(a), "l"(b));
    return d;
}
__device__ __forceinline__ ull pk(float lo, float hi) {
    ull d; asm("mov.b64 %0, {%1, %2};" : "=l"(d) : "f"(lo), "f"(hi));
    return d;
}
__device__ __forceinline__ float hsum(ull v) {
    float lo, hi; asm("mov.b64 {%0, %1}, %2;" : "=f"(lo), "=f"(hi) : "l"(v));
    return lo + hi;
}

__device__ __forceinline__ void bar_sync(int id, int cnt) {
    asm volatile("bar.sync %0, %1;" :: "r"(id), "r"(cnt) : "memory");
}
__device__ __forceinline__ void bar_arrive(int id, int cnt) {
    asm volatile("bar.arrive %0, %1;" :: "r"(id), "r"(cnt) : "memory");
}

// ---------------------------------------------------------------------------
// Kernel 1: GI0[t][g] = (b_ih0[g] + sum_f batch[t][f]*W_ih0[g][f]) * (g<32 ? 0.5 : 1)
// ---------------------------------------------------------------------------
__global__ __launch_bounds__(256) void k_gi0(
    const float* __restrict__ batch,
    const float* __restrict__ Wih0,
    const float* __restrict__ bih0)
{
    __shared__ float Bs[32 * 65];
    __shared__ float Ws[48 * 64];
    const int t0  = blockIdx.x * 32;
    const int tid = threadIdx.x;
    const int tl  = tid & 31;
    const int gg  = tid >> 5;
    const int g0  = gg * 6;

    float acc[6];
#pragma unroll
    for (int j = 0; j < 6; j++) acc[j] = 0.f;

    for (int k0 = 0; k0 < F_IN; k0 += 64) {
        __syncthreads();
#pragma unroll
        for (int i = 0; i < 8; i++) {
            int idx = tid + i * 256;
            int r = idx >> 6, c = idx & 63;
            Bs[r * 65 + c] = batch[(t0 + r) * F_IN + k0 + c];
        }
#pragma unroll
        for (int i = 0; i < 12; i++) {
            int idx = tid + i * 256;
            int r = idx >> 6, c = idx & 63;
            Ws[r * 64 + c] = Wih0[r * F_IN + k0 + c];
        }
        __syncthreads();
#pragma unroll 4
        for (int kk = 0; kk < 64; kk++) {
            float b = Bs[tl * 65 + kk];
#pragma unroll
            for (int j = 0; j < 6; j++) acc[j] += b * Ws[(g0 + j) * 64 + kk];
        }
    }
#pragma unroll
    for (int j = 0; j < 6; j++) {
        float sc = (g0 + j < 32) ? 0.5f : 1.0f;
        g_GI0[(t0 + tl) * GD + g0 + j] = (acc[j] + bih0[g0 + j]) * sc;
    }
}

// ---------------------------------------------------------------------------
// Kernel 2: persistent single-block scan, 3-barrier pipeline (256 threads).
// ---------------------------------------------------------------------------
struct Smem {
    float Wih2[5 * 32 * WROW];   // layers1..5 per-lane [prim16(x0.5)|n16|pad4]
    float Whh2[6 * 32 * WROW];   // prim rows pre-scaled 0.5
    float Wac [6 * 64 * 18];     // attention weights column-major, col slot 18
    float fc1r[32 * 20];
    float ba  [6 * 64];
    float va  [6 * 64];
    float bihN [5 * 16];
    float bhhPr[6 * 32];         // 0.5*(b_hh prim + b_ih prim)
    float bhhN [6 * 16];
    float fc1b[32];
    float fc2 [32];
    float fc2b;
    float pad1[3];
    float h   [6 * 16];
    float newS[6 * 16];
    float ghP [6 * 32];          // published: 0.5*(Whh_p.h + b_hh_p + b_ih_p)
    float ghN [6 * 16];          // published: Whh_n.h + b_hhN
    float e   [36];              // early (l<=3) energies
};

__global__ __launch_bounds__(NT, 1) void k_scan(
    const float* __restrict__ h0,
    const float* __restrict__ W_hh0,
    const float* __restrict__ b_hh0,
    const float* __restrict__ W_ih,
    const float* __restrict__ W_hh,
    const float* __restrict__ b_ih,
    const float* __restrict__ b_hh,
    const float* __restrict__ Wa,
    const float* __restrict__ ba,
    const float* __restrict__ va,
    const float* __restrict__ fc1_w,
    const float* __restrict__ fc1_b,
    const float* __restrict__ fc2_w,
    const float* __restrict__ fc2_b,
    float* __restrict__ out)
{
    extern __shared__ char smem_raw[];
    Smem* s = reinterpret_cast<Smem*>(smem_raw);

    const int tid  = threadIdx.x;
    const int warp = tid >> 5;
    const int lane = tid & 31;
    const int jlow = lane & 15;
    const unsigned FULL = 0xffffffffu;

    // ---------------- build packed layouts in shared (once) ----------------
    for (int idx = tid; idx < 5 * 32 * 16; idx += NT) {
        int hh = idx & 15, r = idx >> 4;
        int l = r >> 5, ln = r & 31;
        s->Wih2[r * WROW + hh]      = 0.5f * W_ih[l * 768 + ln * 16 + hh];
        s->Wih2[r * WROW + 16 + hh] = (ln < 16) ? W_ih[l * 768 + (32 + ln) * 16 + hh] : 0.f;
    }
    for (int idx = tid; idx < 6 * 32 * 16; idx += NT) {
        int hh = idx & 15, r = idx >> 4;
        int i = r >> 5, ln = r & 31;
        float prim, nw;
        if (i == 0) {
            prim = W_hh0[ln * 16 + hh];
            nw   = (ln < 16) ? W_hh0[(32 + ln) * 16 + hh] : 0.f;
        } else {
            prim = W_hh[(i - 1) * 768 + ln * 16 + hh];
            nw   = (ln < 16) ? W_hh[(i - 1) * 768 + (32 + ln) * 16 + hh] : 0.f;
        }
        s->Whh2[r * WROW + hh]      = 0.5f * prim;
        s->Whh2[r * WROW + 16 + hh] = nw;
    }
    for (int idx = tid; idx < 6 * 16 * 64; idx += NT) {
        int i = idx >> 10;
        int rem = idx & 1023;
        int hh = rem >> 6, col = rem & 63;
        s->Wac[(i * 64 + col) * 18 + hh] = Wa[idx];
    }
    for (int idx = tid; idx < 32 * 16; idx += NT) {
        int row = idx >> 4, hh = idx & 15;
        s->fc1r[row * 20 + hh] = fc1_w[idx];
    }
    for (int idx = tid; idx < 6 * 64; idx += NT) { s->ba[idx] = ba[idx]; s->va[idx] = va[idx]; }
    for (int idx = tid; idx < 5 * 16; idx += NT) {
        int l = idx >> 4, j = idx & 15;
        s->bihN[idx] = b_ih[l * 48 + 32 + j];
    }
    for (int idx = tid; idx < 6 * 32; idx += NT) {
        int i = idx >> 5, ln = idx & 31;
        float bp = (i == 0) ? b_hh0[ln] : b_hh[(i - 1) * 48 + ln];
        float bi = (i == 0) ? 0.f : b_ih[(i - 1) * 48 + ln];
        s->bhhPr[idx] = 0.5f * (bp + bi);
    }
    for (int idx = tid; idx < 6 * 16; idx += NT) {
        int i = idx >> 4, j = idx & 15;
        s->bhhN[idx] = (i == 0) ? b_hh0[32 + j] : b_hh[(i - 1) * 48 + 32 + j];
    }
    if (tid < 32) { s->fc1b[tid] = fc1_b[tid]; s->fc2[tid] = fc2_w[tid]; }
    if (tid == 0) s->fc2b = fc2_b[0];
    for (int idx = tid; idx < 6 * 16; idx += NT) s->h[idx] = h0[idx];
    __syncthreads();

    // ---------------- initial gh for step 0 (warps 1..6, i = warp-1) -------
    if (warp >= 1 && warp <= 6) {
        const int i = warp - 1;
        const float* wl = &s->Whh2[(i * 32 + lane) * WROW];
        const ulonglong2* wpv = (const ulonglong2*)wl;
        const ulonglong2* wnv = (const ulonglong2*)(wl + 16);
        const ull* ip = (const ull*)&s->h[i * 16];
        ull p0 = 0ull, p1 = 0ull, q0 = 0ull, q1 = 0ull;
#pragma unroll
        for (int k = 0; k < 4; k++) {
            ulonglong2 wp = wpv[k], wn = wnv[k];
            ull x0 = ip[2 * k], x1 = ip[2 * k + 1];
            p0 = ffma2(wp.x, x0, p0); p1 = ffma2(wp.y, x1, p1);
            q0 = ffma2(wn.x, x0, q0); q1 = ffma2(wn.y, x1, q1);
        }
        s->ghP[i * 32 + lane] = hsum(fadd2(p0, p1)) + s->bhhPr[i * 32 + lane];
        if (lane < 16)
            s->ghN[i * 16 + lane] = hsum(fadd2(q0, q1)) + s->bhhN[i * 16 + lane];
    }
    __syncthreads();

    // =========================== pipeline ===========================
    if (warp == 0) {
        // ------------------ GRU-chain warp (R14 handoff) ------------------
        float gp_cur = g_GI0[lane];             // step-0 prim (pre-halved)
        float gn_cur = g_GI0[32 + jlow];        // step-0 n

        for (int t = 0; t < T_STEPS; t++) {
            // prefetch next step's gi0 scalars (L2-resident; hidden by step)
            float gp_nxt = 0.f, gn_nxt = 0.f;
            if (t + 1 < T_STEPS) {
                gp_nxt = g_GI0[(t + 1) * GD + lane];
                gn_nxt = g_GI0[(t + 1) * GD + 32 + jlow];
            }

            // layer 0 (gi in registers; prim pre-halved incl biases)
            {
                float ap = gp_cur + s->ghP[lane];
                float gv = fmaf(tanh_mufu(ap), 0.5f, 0.5f);
                float zv = __shfl_sync(FULL, gv, 16 + jlow);
                float an = fmaf(gv, s->ghN[jlow], gn_cur);
                float n  = tanh_mufu(an);
                float hp = s->h[jlow];
                float newh = n + zv * (hp - n);
                if (lane < 16) s->newS[lane] = newh;
                __syncwarp();
            }
            // layers 1..5
#pragma unroll
            for (int l = 1; l < LN; l++) {
                const float* wl = &s->Wih2[((l - 1) * 32 + lane) * WROW];
                const ulonglong2* wpv = (const ulonglong2*)wl;
                const ulonglong2* wnv = (const ulonglong2*)(wl + 16);
                const ull* ip = (const ull*)&s->newS[(l - 1) * 16];
                float ghn = s->ghN[l * 16 + jlow];
                float hp  = s->h[l * 16 + jlow];
                ull p0 = pk(s->ghP[l * 32 + lane], 0.f), p1 = 0ull;
                ull q0 = pk(s->bihN[(l - 1) * 16 + jlow], 0.f), q1 = 0ull;
#pragma unroll
                for (int k = 0; k < 4; k++) {
                    ulonglong2 wp = wpv[k], wn = wnv[k];
                    ull x0 = ip[2 * k], x1 = ip[2 * k + 1];
                    p0 = ffma2(wp.x, x0, p0); p1 = ffma2(wp.y, x1, p1);
                    q0 = ffma2(wn.x, x0, q0); q1 = ffma2(wn.y, x1, q1);
                }
                float ap = hsum(fadd2(p0, p1));
                float gv = fmaf(tanh_mufu(ap), 0.5f, 0.5f);
                float zv = __shfl_sync(FULL, gv, 16 + jlow);
                float an = fmaf(gv, ghn, hsum(fadd2(q0, q1)));
                float n  = tanh_mufu(an);
                float newh = n + zv * (hp - n);
                if (lane < 16) s->newS[l * 16 + lane] = newh;
                __syncwarp();
                if (l == 3) bar_arrive(1, NT);      // newS[0..3] ready
            }
            bar_arrive(2, NT);                      // newS[4..5] ready
            bar_sync(3, NT);                        // wait for publishes

            gp_cur = gp_nxt; gn_cur = gn_nxt;
        }
    } else if (warp <= 6) {
        // ------------------ combine warp for layer i = warp-1 ------------------
        const int i = warp - 1;
        ulonglong2 wp_[4], wn_[4];
        {
            const float* whl = &s->Whh2[(i * 32 + lane) * WROW];
            const ulonglong2* wpv = (const ulonglong2*)whl;
            const ulonglong2* wnv = (const ulonglong2*)(whl + 16);
#pragma unroll
            for (int k = 0; k < 4; k++) { wp_[k] = wpv[k]; wn_[k] = wnv[k]; }
        }
        const float bhhP_l = s->bhhPr[i * 32 + lane];
        const float bhhN_l = s->bhhN[i * 16 + jlow];
        const int ne = c_NE[warp - 1], off = c_OFF[warp - 1];

        auto ghS_term = [&](const float* base, float& P, float& N, float& S) {
            const ull* ip = (const ull*)base;
            S = base[jlow];
            ull p0 = 0ull, p1 = 0ull, q0 = 0ull, q1 = 0ull;
#pragma unroll
            for (int k = 0; k < 4; k++) {
                ull x0 = ip[2 * k], x1 = ip[2 * k + 1];
                p0 = ffma2(wp_[k].x, x0, p0); p1 = ffma2(wp_[k].y, x1, p1);
                q0 = ffma2(wn_[k].x, x0, q0); q1 = ffma2(wn_[k].y, x1, q1);
            }
            P = hsum(fadd2(p0, p1));
            N = hsum(fadd2(q0, q1));
        };

        auto energy1 = [&](int ii, int ll) -> float {
            const ull* ip = (const ull*)&s->newS[ll * 16];
            const ull* wa0 = (const ull*)&s->Wac[(ii * 64 + lane) * 18];
            const ull* wa1 = (const ull*)&s->Wac[(ii * 64 + lane + 32) * 18];
            ull a0 = 0ull, a1 = 0ull, a2 = 0ull, a3 = 0ull;
#pragma unroll
            for (int k = 0; k < 4; k++) {
                ull x0 = ip[2 * k], x1 = ip[2 * k + 1];
                a0 = ffma2(wa0[2 * k], x0, a0); a1 = ffma2(wa0[2 * k + 1], x1, a1);
                a2 = ffma2(wa1[2 * k], x0, a2); a3 = ffma2(wa1[2 * k + 1], x1, a3);
            }
            float e0 = hsum(fadd2(a0, a1)) + s->ba[ii * 64 + lane];
            float e1 = hsum(fadd2(a2, a3)) + s->ba[ii * 64 + lane + 32];
            float v = tanh_mufu(e0) * s->va[ii * 64 + lane]
                    + tanh_mufu(e1) * s->va[ii * 64 + lane + 32];
#pragma unroll
            for (int o = 16; o; o >>= 1) v += __shfl_xor_sync(FULL, v, o);
            return v;
        };
        auto energy2 = [&](int iA, int lA, int iB, int lB, float& vA, float& vB) {
            const ull* ipA = (const ull*)&s->newS[lA * 16];
            const ull* ipB = (const ull*)&s->newS[lB * 16];
            const ull* wA0 = (const ull*)&s->Wac[(iA * 64 + lane) * 18];
            const ull* wA1 = (const ull*)&s->Wac[(iA * 64 + lane + 32) * 18];
            const ull* wB0 = (const ull*)&s->Wac[(iB * 64 + lane) * 18];
            const ull* wB1 = (const ull*)&s->Wac[(iB * 64 + lane + 32) * 18];
            ull a0 = 0ull, a1 = 0ull, a2 = 0ull, a3 = 0ull;
            ull b0 = 0ull, b1 = 0ull, b2 = 0ull, b3 = 0ull;
#pragma unroll
            for (int k = 0; k < 4; k++) {
                ull xA0 = ipA[2 * k], xA1 = ipA[2 * k + 1];
                ull xB0 = ipB[2 * k], xB1 = ipB[2 * k + 1];
                a0 = ffma2(wA0[2 * k], xA0, a0); a1 = ffma2(wA0[2 * k + 1], xA1, a1);
                a2 = ffma2(wA1[2 * k], xA0, a2); a3 = ffma2(wA1[2 * k + 1], xA1, a3);
                b0 = ffma2(wB0[2 * k], xB0, b0); b1 = ffma2(wB0[2 * k + 1], xB1, b1);
                b2 = ffma2(wB1[2 * k], xB0, b2); b3 = ffma2(wB1[2 * k + 1], xB1, b3);
            }
            float eA0 = hsum(fadd2(a0, a1)) + s->ba[iA * 64 + lane];
            float eA1 = hsum(fadd2(a2, a3)) + s->ba[iA * 64 + lane + 32];
            float eB0 = hsum(fadd2(b0, b1)) + s->ba[iB * 64 + lane];
            float eB1 = hsum(fadd2(b2, b3)) + s->ba[iB * 64 + lane + 32];
            vA = tanh_mufu(eA0) * s->va[iA * 64 + lane]
               + tanh_mufu(eA1) * s->va[iA * 64 + lane + 32];
            vB = tanh_mufu(eB0) * s->va[iB * 64 + lane]
               + tanh_mufu(eB1) * s->va[iB * 64 + lane + 32];
#pragma unroll
            for (int o = 16; o; o >>= 1) {
                vA += __shfl_xor_sync(FULL, vA, o);
                vB += __shfl_xor_sync(FULL, vB, o);
            }
        };

        for (int t = 0; t < T_STEPS; t++) {
            bar_sync(1, NT);                 // newS[0..3] of step t visible

            float gP[6], gN[6], sv[6];
#pragma unroll
            for (int l = 0; l < 4; l++)
                if (l >= i) ghS_term(&s->newS[l * 16], gP[l], gN[l], sv[l]);
            if (ne == 1) {
                float v = energy1(c_PI[off], c_PL[off]);
                if (lane == 0) s->e[c_PI[off] * 6 + c_PL[off]] = v;
            } else if (ne == 2) {
                float vX, vY;
                energy2(c_PI[off], c_PL[off], c_PI[off + 1], c_PL[off + 1], vX, vY);
                if (lane == 0) {
                    s->e[c_PI[off] * 6 + c_PL[off]] = vX;
                    s->e[c_PI[off + 1] * 6 + c_PL[off + 1]] = vY;
                }
            } else if (ne == 3) {
                float vX, vY;
                energy2(c_PI[off], c_PL[off], c_PI[off + 1], c_PL[off + 1], vX, vY);
                float vZ = energy1(c_PI[off + 2], c_PL[off + 2]);
                if (lane == 0) {
                    s->e[c_PI[off] * 6 + c_PL[off]] = vX;
                    s->e[c_PI[off + 1] * 6 + c_PL[off + 1]] = vY;
                    s->e[c_PI[off + 2] * 6 + c_PL[off + 2]] = vZ;
                }
            }

            bar_sync(2, NT);                 // newS[4..5] + all early e visible

            if (i < 5) {
                // ---- fused tail: one pass over x4/x5 + shared Wa columns ----
                const ull* ip4 = (const ull*)&s->newS[4 * 16];
                const ull* ip5 = (const ull*)&s->newS[5 * 16];
                sv[4] = s->newS[4 * 16 + jlow];
                sv[5] = s->newS[5 * 16 + jlow];
                const ull* wa0 = (const ull*)&s->Wac[(i * 64 + lane) * 18];
                const ull* wa1 = (const ull*)&s->Wac[(i * 64 + lane + 32) * 18];
                ull p40 = 0ull, p41 = 0ull, q40 = 0ull, q41 = 0ull;
                ull p50 = 0ull, p51 = 0ull, q50 = 0ull, q51 = 0ull;
                ull a0 = 0ull, a1 = 0ull, a2 = 0ull, a3 = 0ull;
                ull b0 = 0ull, b1 = 0ull, b2 = 0ull, b3 = 0ull;
#pragma unroll
                for (int k = 0; k < 4; k++) {
                    ull x40 = ip4[2 * k], x41 = ip4[2 * k + 1];
                    ull x50 = ip5[2 * k], x51 = ip5[2 * k + 1];
                    ull w0 = wa0[2 * k], w1 = wa0[2 * k + 1];
                    ull u0 = wa1[2 * k], u1 = wa1[2 * k + 1];
                    p40 = ffma2(wp_[k].x, x40, p40); p41 = ffma2(wp_[k].y, x41, p41);
                    q40 = ffma2(wn_[k].x, x40, q40); q41 = ffma2(wn_[k].y, x41, q41);
                    p50 = ffma2(wp_[k].x, x50, p50); p51 = ffma2(wp_[k].y, x51, p51);
                    q50 = ffma2(wn_[k].x, x50, q50); q51 = ffma2(wn_[k].y, x51, q51);
                    a0 = ffma2(w0, x40, a0); a1 = ffma2(w1, x41, a1);
                    a2 = ffma2(u0, x40, a2); a3 = ffma2(u1, x41, a3);
                    b0 = ffma2(w0, x50, b0); b1 = ffma2(w1, x51, b1);
                    b2 = ffma2(u0, x50, b2); b3 = ffma2(u1, x51, b3);
                }
                gP[4] = hsum(fadd2(p40, p41)); gN[4] = hsum(fadd2(q40, q41));
                gP[5] = hsum(fadd2(p50, p51)); gN[5] = hsum(fadd2(q50, q51));
                float bac0 = s->ba[i * 64 + lane], bac1 = s->ba[i * 64 + lane + 32];
                float vac0 = s->va[i * 64 + lane], vac1 = s->va[i * 64 + lane + 32];
                float vA = tanh_mufu(hsum(fadd2(a0, a1)) + bac0) * vac0
                         + tanh_mufu(hsum(fadd2(a2, a3)) + bac1) * vac1;
                float vB = tanh_mufu(hsum(fadd2(b0, b1)) + bac0) * vac0
                         + tanh_mufu(hsum(fadd2(b2, b3)) + bac1) * vac1;
#pragma unroll
                for (int o = 16; o; o >>= 1) {
                    vA += __shfl_xor_sync(FULL, vA, o);
                    vB += __shfl_xor_sync(FULL, vB, o);
                }
                // softmax without max-subtraction (|e| bounded ~5)
                float evl[6];
                evl[4] = vA; evl[5] = vB;
#pragma unroll
                for (int l = 0; l < 4; l++)
                    if (l >= i) evl[l] = s->e[i * 6 + l];
                float wv[6], ssum = 0.f;
#pragma unroll
                for (int l = 0; l < 6; l++)
                    if (l >= i) { wv[l] = __expf(evl[l]); ssum += wv[l]; }
                float inv = __fdividef(1.f, ssum);
                float sP = 0.f, sN = 0.f, sH = 0.f;
#pragma unroll
                for (int l = 0; l < 6; l++)
                    if (l >= i) {
                        sP += wv[l] * gP[l];
                        sN += wv[l] * gN[l];
                        sH += wv[l] * sv[l];
                    }
                s->ghP[i * 32 + lane] = bhhP_l + sP * inv;
                if (lane < 16) {
                    s->ghN[i * 16 + lane] = bhhN_l + sN * inv;
                    s->h[i * 16 + lane]   = sH * inv;
                }
            } else {
                // i = 5: h_next = newS[5]; gh direct
                ghS_term(&s->newS[5 * 16], gP[5], gN[5], sv[5]);
                s->ghP[5 * 32 + lane] = bhhP_l + gP[5];
                if (lane < 16) {
                    s->ghN[5 * 16 + lane] = bhhN_l + gN[5];
                    s->h[5 * 16 + lane]   = sv[5];
                }
            }
            __syncwarp();
            bar_arrive(3, NT);               // step-(t+1) state published
        }
    } else {
        // ------------------ warp 7: early energies + FC head ------------------
        const int off = c_OFF[6];
        const ull* fw = (const ull*)&s->fc1r[lane * 20];
        const float fc1b_l = s->fc1b[lane], fc2_l = s->fc2[lane];

        auto energy1 = [&](int ii, int ll) -> float {
            const ull* ip = (const ull*)&s->newS[ll * 16];
            const ull* wa0 = (const ull*)&s->Wac[(ii * 64 + lane) * 18];
            const ull* wa1 = (const ull*)&s->Wac[(ii * 64 + lane + 32) * 18];
            ull a0 = 0ull, a1 = 0ull, a2 = 0ull, a3 = 0ull;
#pragma unroll
            for (int k = 0; k < 4; k++) {
                ull x0 = ip[2 * k], x1 = ip[2 * k + 1];
                a0 = ffma2(wa0[2 * k], x0, a0); a1 = ffma2(wa0[2 * k + 1], x1, a1);
                a2 = ffma2(wa1[2 * k], x0, a2); a3 = ffma2(wa1[2 * k + 1], x1, a3);
            }
            float e0 = hsum(fadd2(a0, a1)) + s->ba[ii * 64 + lane];
            float e1 = hsum(fadd2(a2, a3)) + s->ba[ii * 64 + lane + 32];
            float v = tanh_mufu(e0) * s->va[ii * 64 + lane]
                    + tanh_mufu(e1) * s->va[ii * 64 + lane + 32];
#pragma unroll
            for (int o = 16; o; o >>= 1) v += __shfl_xor_sync(FULL, v, o);
            return v;
        };

        for (int t = 0; t < T_STEPS; t++) {
            bar_sync(1, NT);
            {
                float v0 = energy1(c_PI[off], c_PL[off]);
                float v1 = energy1(c_PI[off + 1], c_PL[off + 1]);
                if (lane == 0) {
                    s->e[c_PI[off] * 6 + c_PL[off]] = v0;
                    s->e[c_PI[off + 1] * 6 + c_PL[off + 1]] = v1;
                }
            }
            bar_sync(2, NT);                 // newS[5] visible
            {
                const ull* ip = (const ull*)&s->newS[5 * 16];
                ull a0 = 0ull, a1 = 0ull;
#pragma unroll
                for (int k = 0; k < 4; k++) {
                    a0 = ffma2(fw[2 * k], ip[2 * k], a0);
                    a1 = ffma2(fw[2 * k + 1], ip[2 * k + 1], a1);
                }
                float acc = (hsum(fadd2(a0, a1)) + fc1b_l) * fc2_l;
#pragma unroll
                for (int o = 16; o; o >>= 1)
                    acc += __shfl_xor_sync(FULL, acc, o);
                if (lane == 0) out[t] = acc + s->fc2b;
            }
            __syncwarp();
            bar_arrive(3, NT);
        }
    }
}

// ---------------------------------------------------------------------------
extern "C" void kernel_launch(void* const* d_in, const int* in_sizes, int n_in,
                              void* d_out, int out_size)
{
    const float* batch  = (const float*)d_in[0];
    const float* h0     = (const float*)d_in[1];
    const float* W_ih0  = (const float*)d_in[2];
    const float* W_hh0  = (const float*)d_in[3];
    const float* b_ih0  = (const float*)d_in[4];
    const float* b_hh0  = (const float*)d_in[5];
    const float* W_ih   = (const float*)d_in[6];
    const float* W_hh   = (const float*)d_in[7];
    const float* b_ih   = (const float*)d_in[8];
    const float* b_hh   = (const float*)d_in[9];
    const float* Wa     = (const float*)d_in[10];
    const float* ba     = (const float*)d_in[11];
    const float* va     = (const float*)d_in[12];
    const float* fc1_w  = (const float*)d_in[13];
    const float* fc1_b  = (const float*)d_in[14];
    const float* fc2_w  = (const float*)d_in[15];
    const float* fc2_b  = (const float*)d_in[16];
    float* out = (float*)d_out;

    cudaFuncSetAttribute(k_scan, cudaFuncAttributeMaxDynamicSharedMemorySize,
                         (int)sizeof(Smem));

    k_gi0<<<T_STEPS / 32, 256>>>(batch, W_ih0, b_ih0);
    k_scan<<<1, NT, sizeof(Smem)>>>(h0, W_hh0, b_hh0, W_ih, W_hh, b_ih, b_hh,
                                    Wa, ba, va, fc1_w, fc1_b, fc2_w, fc2_b, out);
}